// round 2
// baseline (speedup 1.0000x reference)
#include <cuda_runtime.h>
#include <cuda_bf16.h>

#define BATCH      524288
#define N_QUBITS   16
#define NUM_CLS    10
#define TPB        128           // 4 warps
#define RPT        4             // rows per thread
#define ROWS_PER_WARP   (32 * RPT)          // 128
#define ROWS_PER_BLOCK  (TPB * RPT)         // 512

// Output[b, s] = tail_s / sum_{s'<10} tail_s' where tail depends only on
// qubits 12..15 (states 0..9 have zero bits for qubits 0..11; the common
// prod_{i<12} p0_i factor cancels in the normalization).
__global__ __launch_bounds__(TPB) void qllp_kernel(
    const float* __restrict__ x,       // [BATCH, 16]
    const float* __restrict__ params,  // [16]
    float*       __restrict__ out)     // [BATCH, 10]
{
    // Per-warp staging slices: 128 rows * 10 floats = 1280 floats (5 KB) each.
    __shared__ float s_out[(TPB / 32) * ROWS_PER_WARP * NUM_CLS];   // 20 KB

    const int lane  = threadIdx.x & 31;
    const int warp  = threadIdx.x >> 5;
    const int wbase = blockIdx.x * ROWS_PER_BLOCK + warp * ROWS_PER_WARP;

    float* s_warp = s_out + warp * (ROWS_PER_WARP * NUM_CLS);

    const float pr12 = __ldg(&params[12]);
    const float pr13 = __ldg(&params[13]);
    const float pr14 = __ldg(&params[14]);
    const float pr15 = __ldg(&params[15]);

    // Front-batched independent loads: MLP=4 per thread.
    float4 v[RPT];
    #pragma unroll
    for (int j = 0; j < RPT; j++) {
        const int row = wbase + lane + 32 * j;
        v[j] = *reinterpret_cast<const float4*>(x + (size_t)row * N_QUBITS + 12);
    }

    const float PI = 3.14159265358979323846f;

    #pragma unroll
    for (int j = 0; j < RPT; j++) {
        const float h0 = (PI * v[j].x + pr12) * 0.5f;  // qubit 12
        const float h1 = (PI * v[j].y + pr13) * 0.5f;  // qubit 13
        const float h2 = (PI * v[j].z + pr14) * 0.5f;  // qubit 14
        const float h3 = (PI * v[j].w + pr15) * 0.5f;  // qubit 15

        float sn, cs;
        sincosf(h0, &sn, &cs); const float a0 = cs * cs, b0 = sn * sn;
        sincosf(h1, &sn, &cs); const float a1 = cs * cs, b1 = sn * sn;
        sincosf(h2, &sn, &cs); const float a2 = cs * cs, b2 = sn * sn;
        sincosf(h3, &sn, &cs); const float a3 = cs * cs, b3 = sn * sn;

        // bits[s,i] = (s >> (15-i)) & 1 -> qubit12 = bit3 ... qubit15 = bit0
        const float m00 = a1 * a2, m01 = a1 * b2, m10 = b1 * a2, m11 = b1 * b2;
        const float g0 = m00 * a3, g1 = m00 * b3, g2 = m01 * a3, g3 = m01 * b3;
        const float g4 = m10 * a3, g5 = m10 * b3, g6 = m11 * a3, g7 = m11 * b3;

        float t[NUM_CLS];
        t[0] = a0 * g0;  t[1] = a0 * g1;  t[2] = a0 * g2;  t[3] = a0 * g3;
        t[4] = a0 * g4;  t[5] = a0 * g5;  t[6] = a0 * g6;  t[7] = a0 * g7;
        t[8] = b0 * g0;  t[9] = b0 * g1;

        float sum = t[0];
        #pragma unroll
        for (int s = 1; s < NUM_CLS; s++) sum += t[s];
        const float inv = 1.0f / sum;

        float* dst = s_warp + (lane + 32 * j) * NUM_CLS;
        #pragma unroll
        for (int s = 0; s < NUM_CLS; s++) dst[s] = t[s] * inv;
    }

    __syncwarp();

    // Warp-local dense writeback: 128 rows * 10 floats = 320 float4,
    // 10 per lane, fully coalesced, conflict-free LDS.
    float4* o4 = reinterpret_cast<float4*>(out + (size_t)wbase * NUM_CLS);
    const float4* s4 = reinterpret_cast<const float4*>(s_warp);
    #pragma unroll
    for (int i = 0; i < (ROWS_PER_WARP * NUM_CLS) / (4 * 32); i++)   // 10 iters
        o4[i * 32 + lane] = s4[i * 32 + lane];
}

extern "C" void kernel_launch(void* const* d_in, const int* in_sizes, int n_in,
                              void* d_out, int out_size) {
    const float* x      = (const float*)d_in[0];
    const float* params = (const float*)d_in[1];
    float*       out    = (float*)d_out;
    qllp_kernel<<<BATCH / ROWS_PER_BLOCK, TPB>>>(x, params, out);
}

// round 3
// speedup vs baseline: 1.0320x; 1.0320x over previous
#include <cuda_runtime.h>
#include <cuda_bf16.h>

#define BATCH      524288
#define N_QUBITS   16
#define NUM_CLS    10
#define TPB        256           // 8 warps, 1 row per thread

// Output[b, s] = tail_s / sum_{s'<10} tail_s' where tail depends only on
// qubits 12..15 (states 0..9 have zero bits for qubits 0..11; the common
// prod_{i<12} p0_i factor cancels in the normalization).
//
// Half-angle elimination:  cos^2(theta/2) = (1+cos theta)/2,
//                          sin^2(theta/2) = (1-cos theta)/2
// -> one __cosf per qubit instead of an accurate sincosf of the half angle.
__global__ __launch_bounds__(TPB) void qllp_kernel(
    const float* __restrict__ x,       // [BATCH, 16]
    const float* __restrict__ params,  // [16]
    float*       __restrict__ out)     // [BATCH, 10]
{
    // Per-warp staging: 32 rows * 10 floats = 320 floats (1.25 KB) per warp.
    __shared__ float s_out[TPB * NUM_CLS];   // 10 KB

    const int lane = threadIdx.x & 31;
    const int warp = threadIdx.x >> 5;
    const int row  = blockIdx.x * TPB + threadIdx.x;

    float* s_warp = s_out + warp * (32 * NUM_CLS);

    // Aligned 16B load of x[row, 12..15].
    const float4 v = *reinterpret_cast<const float4*>(x + (size_t)row * N_QUBITS + 12);

    const float pr12 = __ldg(&params[12]);
    const float pr13 = __ldg(&params[13]);
    const float pr14 = __ldg(&params[14]);
    const float pr15 = __ldg(&params[15]);

    const float PI = 3.14159265358979323846f;
    // Full angles (NOT half): theta_i = pi*x_i + p_i
    const float c0 = __cosf(PI * v.x + pr12);   // qubit 12
    const float c1 = __cosf(PI * v.y + pr13);   // qubit 13
    const float c2 = __cosf(PI * v.z + pr14);   // qubit 14
    const float c3 = __cosf(PI * v.w + pr15);   // qubit 15

    const float a0 = 0.5f + 0.5f * c0, b0 = 0.5f - 0.5f * c0;
    const float a1 = 0.5f + 0.5f * c1, b1 = 0.5f - 0.5f * c1;
    const float a2 = 0.5f + 0.5f * c2, b2 = 0.5f - 0.5f * c2;
    const float a3 = 0.5f + 0.5f * c3, b3 = 0.5f - 0.5f * c3;

    // bits[s,i] = (s >> (15-i)) & 1 -> qubit12 = bit3 ... qubit15 = bit0
    const float m00 = a1 * a2, m01 = a1 * b2, m10 = b1 * a2, m11 = b1 * b2;
    const float g0 = m00 * a3, g1 = m00 * b3, g2 = m01 * a3, g3 = m01 * b3;
    const float g4 = m10 * a3, g5 = m10 * b3, g6 = m11 * a3, g7 = m11 * b3;

    float t[NUM_CLS];
    t[0] = a0 * g0;  t[1] = a0 * g1;  t[2] = a0 * g2;  t[3] = a0 * g3;
    t[4] = a0 * g4;  t[5] = a0 * g5;  t[6] = a0 * g6;  t[7] = a0 * g7;
    t[8] = b0 * g0;  t[9] = b0 * g1;

    float sum = t[0];
    #pragma unroll
    for (int s = 1; s < NUM_CLS; s++) sum += t[s];
    const float inv = __fdividef(1.0f, sum);

    float* dst = s_warp + lane * NUM_CLS;
    #pragma unroll
    for (int s = 0; s < NUM_CLS; s++) dst[s] = t[s] * inv;

    __syncwarp();

    // Warp-local dense writeback: 320 floats = 160 float2, 5 per lane,
    // fully coalesced STG.64. No block barrier -> warps run unphased.
    float2* o2 = reinterpret_cast<float2*>(
        out + ((size_t)blockIdx.x * TPB + warp * 32) * NUM_CLS);
    const float2* s2 = reinterpret_cast<const float2*>(s_warp);
    #pragma unroll
    for (int i = 0; i < (32 * NUM_CLS) / (2 * 32); i++)   // 5 iters
        o2[i * 32 + lane] = s2[i * 32 + lane];
}

extern "C" void kernel_launch(void* const* d_in, const int* in_sizes, int n_in,
                              void* d_out, int out_size) {
    const float* x      = (const float*)d_in[0];
    const float* params = (const float*)d_in[1];
    float*       out    = (float*)d_out;
    qllp_kernel<<<BATCH / TPB, TPB>>>(x, params, out);
}

// round 4
// speedup vs baseline: 1.3100x; 1.2694x over previous
#include <cuda_runtime.h>
#include <cuda_bf16.h>

#define BATCH      524288
#define N_QUBITS   16
#define NUM_CLS    10
#define TPB        256            // 8 warps
#define RPT        2              // rows per thread, loads front-batched (MLP=2)
#define ROWS_PER_BLOCK (TPB * RPT)   // 512

// Output[b, s] = tail_s / sum_{s'<10} tail_s' where tail depends only on
// qubits 12..15 (states 0..9 have zero bits for qubits 0..11; the common
// prod_{i<12} p0_i factor cancels in the normalization).
// Half-angle elimination: cos^2(t/2) = (1+cos t)/2, sin^2(t/2) = (1-cos t)/2.
__global__ __launch_bounds__(TPB, 6) void qllp_kernel(
    const float* __restrict__ x,       // [BATCH, 16]
    const float* __restrict__ params,  // [16]
    float*       __restrict__ out)     // [BATCH, 10]
{
    // Per-warp staging: 64 rows * 10 floats = 2.5 KB per warp, 20 KB total.
    __shared__ float s_out[(TPB / 32) * 64 * NUM_CLS];

    const int lane = threadIdx.x & 31;
    const int warp = threadIdx.x >> 5;
    // Warp w owns rows [wbase, wbase + 64).
    const int wbase = blockIdx.x * ROWS_PER_BLOCK + warp * (32 * RPT);

    float* s_warp = s_out + warp * (64 * NUM_CLS);

    const float pr12 = __ldg(&params[12]);
    const float pr13 = __ldg(&params[13]);
    const float pr14 = __ldg(&params[14]);
    const float pr15 = __ldg(&params[15]);

    // Front-batched independent 16B loads: 2 outstanding per thread.
    float4 v[RPT];
    #pragma unroll
    for (int j = 0; j < RPT; j++) {
        const int row = wbase + 32 * j + lane;
        v[j] = *reinterpret_cast<const float4*>(x + (size_t)row * N_QUBITS + 12);
    }

    const float PI = 3.14159265358979323846f;

    #pragma unroll
    for (int j = 0; j < RPT; j++) {
        const float c0 = __cosf(PI * v[j].x + pr12);   // qubit 12
        const float c1 = __cosf(PI * v[j].y + pr13);   // qubit 13
        const float c2 = __cosf(PI * v[j].z + pr14);   // qubit 14
        const float c3 = __cosf(PI * v[j].w + pr15);   // qubit 15

        const float a0 = 0.5f + 0.5f * c0, b0 = 0.5f - 0.5f * c0;
        const float a1 = 0.5f + 0.5f * c1, b1 = 0.5f - 0.5f * c1;
        const float a2 = 0.5f + 0.5f * c2, b2 = 0.5f - 0.5f * c2;
        const float a3 = 0.5f + 0.5f * c3, b3 = 0.5f - 0.5f * c3;

        // bits[s,i] = (s >> (15-i)) & 1 -> qubit12 = bit3 ... qubit15 = bit0
        const float m00 = a1 * a2, m01 = a1 * b2, m10 = b1 * a2, m11 = b1 * b2;
        const float g0 = m00 * a3, g1 = m00 * b3, g2 = m01 * a3, g3 = m01 * b3;
        const float g4 = m10 * a3, g5 = m10 * b3, g6 = m11 * a3, g7 = m11 * b3;

        float t[NUM_CLS];
        t[0] = a0 * g0;  t[1] = a0 * g1;  t[2] = a0 * g2;  t[3] = a0 * g3;
        t[4] = a0 * g4;  t[5] = a0 * g5;  t[6] = a0 * g6;  t[7] = a0 * g7;
        t[8] = b0 * g0;  t[9] = b0 * g1;

        float sum = t[0];
        #pragma unroll
        for (int s = 1; s < NUM_CLS; s++) sum += t[s];
        const float inv = __fdividef(1.0f, sum);

        float* dst = s_warp + (32 * j + lane) * NUM_CLS;
        #pragma unroll
        for (int s = 0; s < NUM_CLS; s++) dst[s] = t[s] * inv;
    }

    __syncwarp();

    // Warp-local dense writeback: 64 rows * 10 floats = 320 float2,
    // 10 per lane, fully coalesced STG.64. No block barrier.
    float2* o2 = reinterpret_cast<float2*>(out + (size_t)wbase * NUM_CLS);
    const float2* s2 = reinterpret_cast<const float2*>(s_warp);
    #pragma unroll
    for (int i = 0; i < (64 * NUM_CLS) / (2 * 32); i++)   // 10 iters
        o2[i * 32 + lane] = s2[i * 32 + lane];
}

extern "C" void kernel_launch(void* const* d_in, const int* in_sizes, int n_in,
                              void* d_out, int out_size) {
    const float* x      = (const float*)d_in[0];
    const float* params = (const float*)d_in[1];
    float*       out    = (float*)d_out;
    qllp_kernel<<<BATCH / ROWS_PER_BLOCK, TPB>>>(x, params, out);
}